// round 9
// baseline (speedup 1.0000x reference)
#include <cuda_runtime.h>
#include <math.h>

// Problem constants (fixed by setup_inputs)
#define B_    128
#define T_    320000
#define NB_   32            // reduction blocks per row
#define SLICE (T_ / NB_)    // 10000 (divisible by 4)
#define TILE  4096
#define HALO  16            // max half = 16 (k up to 33)
#define NT3   256
#define PER_TH (TILE / NT3) // 16 samples per thread

#define GAIN_PROB   0.7f
#define NOISE_PROB  0.5f
#define FILTER_PROB 0.35f

// Conflict-free index mapping for stride-16 access patterns:
// bank(16*l + l/2) hits all 32 banks for l = 0..31.
#define SIDX(i) ((i) + ((i) >> 5))
#define SMEM_LOGICAL (TILE + 2 * HALO + 1)              // 4129 (incl. 1 pad slot for final slide)
#define SMEM_PHYS    (SMEM_LOGICAL + (SMEM_LOGICAL >> 5) + 1)

// Scratch (no cudaMalloc allowed)
__device__ float g_psum[B_ * NB_];
__device__ float g_psq [B_ * NB_];
__device__ float g_gain [B_];
__device__ float g_ncoef[B_];
__device__ float g_invk [B_];
__device__ int   g_half [B_];
__device__ int   g_mode [B_];   // 0 = passthrough, 1 = low-pass, 2 = high-pass

// ---------------------------------------------------------------------------
// Pass 1: per-row partial sum / sum-of-squares of raw x (std(x1) = g * std(x)).
// Rows that won't get noise skip the read entirely.
// ---------------------------------------------------------------------------
__global__ void k_reduce(const float* __restrict__ x,
                         const float* __restrict__ do_noise) {
    const int b = blockIdx.y;
    if (do_noise[b] >= NOISE_PROB) return;   // partials unused for this row

    const int nb = blockIdx.x;
    const float4* xv = (const float4*)(x + (size_t)b * T_ + (size_t)nb * SLICE);

    float s = 0.f, q = 0.f;
    for (int i = threadIdx.x; i < SLICE / 4; i += blockDim.x) {
        float4 v = xv[i];
        s += v.x + v.y + v.z + v.w;
        q += v.x * v.x + v.y * v.y + v.z * v.z + v.w * v.w;
    }
    // warp reduce
    #pragma unroll
    for (int o = 16; o; o >>= 1) {
        s += __shfl_down_sync(0xffffffffu, s, o);
        q += __shfl_down_sync(0xffffffffu, q, o);
    }
    __shared__ float ss[8], sq[8];
    const int w = threadIdx.x >> 5, l = threadIdx.x & 31;
    if (l == 0) { ss[w] = s; sq[w] = q; }
    __syncthreads();
    if (threadIdx.x == 0) {
        float S = 0.f, Q = 0.f;
        #pragma unroll
        for (int i = 0; i < 8; i++) { S += ss[i]; Q += sq[i]; }
        g_psum[b * NB_ + nb] = S;
        g_psq [b * NB_ + nb] = Q;
    }
}

// ---------------------------------------------------------------------------
// Pass 2: fold all per-row scalars (gain, noise coefficient, filter params).
// ---------------------------------------------------------------------------
__global__ void k_finalize(const float* __restrict__ gains,
                           const float* __restrict__ noise_scales,
                           const float* __restrict__ do_gain,
                           const float* __restrict__ do_noise,
                           const float* __restrict__ do_filter,
                           const float* __restrict__ low_coin,
                           const int*   __restrict__ halves) {
    const int b = threadIdx.x;
    if (b >= B_) return;

    const float g = (do_gain[b] < GAIN_PROB) ? gains[b] : 1.0f;
    g_gain[b] = g;

    float nc = 0.f;
    if (do_noise[b] < NOISE_PROB) {
        float S = 0.f, Q = 0.f;
        #pragma unroll 8
        for (int i = 0; i < NB_; i++) { S += g_psum[b * NB_ + i]; Q += g_psq[b * NB_ + i]; }
        const float N = (float)T_;
        float var = (Q - S * S / N) / (N - 1.0f);
        var = fmaxf(var, 0.f);
        float sd = g * sqrtf(var);       // std(x * g) = g * std(x), g > 0
        sd = fmaxf(sd, 1e-4f);           // clip
        nc = sd * noise_scales[b];
    }
    g_ncoef[b] = nc;

    const int h = halves[b];
    g_half[b] = h;
    g_invk[b] = 1.0f / (float)(2 * h + 1);

    int mode = 0;
    if (do_filter[b] < FILTER_PROB) mode = (low_coin[b] < 0.5f) ? 1 : 2;
    g_mode[b] = mode;
}

// ---------------------------------------------------------------------------
// Pass 3: main elementwise + moving-average kernel.
//   mode 0: pure float4 streaming (no SMEM)
//   mode 1/2: SMEM tile of x2 with halo, per-thread sliding window sum
// ---------------------------------------------------------------------------
__global__ __launch_bounds__(NT3) void k_main(const float* __restrict__ x,
                                              const float* __restrict__ noise,
                                              float* __restrict__ out) {
    const int b  = blockIdx.y;
    const int t0 = blockIdx.x * TILE;
    const int mode = g_mode[b];
    const float gain = g_gain[b];
    const float nc   = g_ncoef[b];
    const size_t base = (size_t)b * T_;
    const int count = min(TILE, T_ - t0);

    if (mode == 0) {
        // Streaming path. T_ and TILE divisible by 4 -> full float4 coverage.
        const int n4 = count >> 2;
        const float4* xv = (const float4*)(x + base + t0);
        const float4* nv = (const float4*)(noise + base + t0);
        float4* ov = (float4*)(out + base + t0);
        if (nc != 0.f) {
            for (int i = threadIdx.x; i < n4; i += NT3) {
                float4 a = xv[i], n = nv[i], o;
                o.x = fmaf(n.x, nc, a.x * gain);
                o.y = fmaf(n.y, nc, a.y * gain);
                o.z = fmaf(n.z, nc, a.z * gain);
                o.w = fmaf(n.w, nc, a.w * gain);
                ov[i] = o;
            }
        } else {
            for (int i = threadIdx.x; i < n4; i += NT3) {
                float4 a = xv[i], o;
                o.x = a.x * gain; o.y = a.y * gain;
                o.z = a.z * gain; o.w = a.w * gain;
                ov[i] = o;
            }
        }
        return;
    }

    // Filter path: build x2 tile (with halo, zero outside [0,T)) in SMEM.
    __shared__ float s[SMEM_PHYS];
    if (nc != 0.f) {
        for (int i = threadIdx.x; i < SMEM_LOGICAL; i += NT3) {
            const int t = t0 - HALO + i;
            float v = 0.f;
            if (t >= 0 && t < T_) v = fmaf(noise[base + t], nc, x[base + t] * gain);
            s[SIDX(i)] = v;
        }
    } else {
        for (int i = threadIdx.x; i < SMEM_LOGICAL; i += NT3) {
            const int t = t0 - HALO + i;
            float v = 0.f;
            if (t >= 0 && t < T_) v = x[base + t] * gain;
            s[SIDX(i)] = v;
        }
    }
    __syncthreads();

    const int h = g_half[b];
    const float invk = g_invk[b];
    const int j0 = threadIdx.x * PER_TH;
    if (j0 < count) {
        const int c = HALO + j0;   // smem logical index of first sample
        float sum = 0.f;
        for (int d = -h; d <= h; d++) sum += s[SIDX(c + d)];

        const int lim = min(PER_TH, count - j0);
        float* op = out + base + t0 + j0;
        #pragma unroll
        for (int j = 0; j < PER_TH; j++) {
            if (j >= lim) break;
            const float ctr = s[SIDX(c + j)];
            const float low = sum * invk;
            op[j] = (mode == 1) ? low : (ctr - low);
            sum += s[SIDX(c + j + 1 + h)] - s[SIDX(c + j - h)];
        }
    }
}

// ---------------------------------------------------------------------------
extern "C" void kernel_launch(void* const* d_in, const int* in_sizes, int n_in,
                              void* d_out, int out_size) {
    const float* x            = (const float*)d_in[0];
    const float* gains        = (const float*)d_in[1];
    const float* noise_scales = (const float*)d_in[2];
    const float* noise        = (const float*)d_in[3];
    const float* do_gain      = (const float*)d_in[4];
    const float* do_noise     = (const float*)d_in[5];
    const float* do_filter    = (const float*)d_in[6];
    const float* low_coin     = (const float*)d_in[7];
    const int*   halves       = (const int*)  d_in[8];
    float* out = (float*)d_out;

    dim3 g1(NB_, B_);
    k_reduce<<<g1, 256>>>(x, do_noise);
    k_finalize<<<1, 128>>>(gains, noise_scales, do_gain, do_noise,
                           do_filter, low_coin, halves);
    dim3 g3((T_ + TILE - 1) / TILE, B_);
    k_main<<<g3, NT3>>>(x, noise, out);
}

// round 10
// speedup vs baseline: 1.1569x; 1.1569x over previous
#include <cuda_runtime.h>
#include <math.h>

// Problem constants (fixed by setup_inputs)
#define B_    128
#define T_    320000
#define NB_   32            // reduction blocks per row
#define SLICE (T_ / NB_)    // 10000 (divisible by 4)
#define TILE  4096
#define HALO  16            // max half = 16 (k up to 33)
#define NT3   256
#define PER_TH (TILE / NT3) // 16 samples per thread

#define GAIN_PROB   0.7f
#define NOISE_PROB  0.5f
#define FILTER_PROB 0.35f

// Conflict-free index mapping for stride-16 access patterns:
// bank(16*l + (16*l+j)>>5) hits all 32 banks for l = 0..31.
#define SIDX(i) ((i) + ((i) >> 5))
#define SMEM_LOGICAL (TILE + 2 * HALO + 1)              // 4129 (incl. 1 pad slot for final slide)
#define SMEM_PHYS    (SMEM_LOGICAL + (SMEM_LOGICAL >> 5) + 1)
#define OUT_PHYS     (TILE + (TILE >> 5))               // staging buffer, SIDX-padded

// Scratch (no cudaMalloc allowed)
__device__ float g_psum[B_ * NB_];
__device__ float g_psq [B_ * NB_];
__device__ float g_gain [B_];
__device__ float g_ncoef[B_];
__device__ float g_invk [B_];
__device__ int   g_half [B_];
__device__ int   g_mode [B_];   // 0 = passthrough, 1 = low-pass, 2 = high-pass

// ---------------------------------------------------------------------------
// Pass 1: per-row partial sum / sum-of-squares of raw x (std(x1) = g * std(x)).
// Rows that won't get noise skip the read entirely.
// ---------------------------------------------------------------------------
__global__ void k_reduce(const float* __restrict__ x,
                         const float* __restrict__ do_noise) {
    const int b = blockIdx.y;
    if (do_noise[b] >= NOISE_PROB) return;   // partials unused for this row

    const int nb = blockIdx.x;
    const float4* xv = (const float4*)(x + (size_t)b * T_ + (size_t)nb * SLICE);

    // Two independent accumulator pairs + unroll -> more LDG.128 in flight.
    float s0 = 0.f, q0 = 0.f, s1 = 0.f, q1 = 0.f;
    #pragma unroll 4
    for (int i = threadIdx.x; i < SLICE / 4; i += 2 * blockDim.x) {
        float4 v = xv[i];
        s0 += v.x + v.y + v.z + v.w;
        q0 += v.x * v.x + v.y * v.y + v.z * v.z + v.w * v.w;
        const int i2 = i + blockDim.x;
        if (i2 < SLICE / 4) {
            float4 u = xv[i2];
            s1 += u.x + u.y + u.z + u.w;
            q1 += u.x * u.x + u.y * u.y + u.z * u.z + u.w * u.w;
        }
    }
    float s = s0 + s1, q = q0 + q1;
    // warp reduce
    #pragma unroll
    for (int o = 16; o; o >>= 1) {
        s += __shfl_down_sync(0xffffffffu, s, o);
        q += __shfl_down_sync(0xffffffffu, q, o);
    }
    __shared__ float ss[8], sq[8];
    const int w = threadIdx.x >> 5, l = threadIdx.x & 31;
    if (l == 0) { ss[w] = s; sq[w] = q; }
    __syncthreads();
    if (threadIdx.x == 0) {
        float S = 0.f, Q = 0.f;
        #pragma unroll
        for (int i = 0; i < 8; i++) { S += ss[i]; Q += sq[i]; }
        g_psum[b * NB_ + nb] = S;
        g_psq [b * NB_ + nb] = Q;
    }
}

// ---------------------------------------------------------------------------
// Pass 2: fold all per-row scalars (gain, noise coefficient, filter params).
// ---------------------------------------------------------------------------
__global__ void k_finalize(const float* __restrict__ gains,
                           const float* __restrict__ noise_scales,
                           const float* __restrict__ do_gain,
                           const float* __restrict__ do_noise,
                           const float* __restrict__ do_filter,
                           const float* __restrict__ low_coin,
                           const int*   __restrict__ halves) {
    const int b = threadIdx.x;
    if (b >= B_) return;

    const float g = (do_gain[b] < GAIN_PROB) ? gains[b] : 1.0f;
    g_gain[b] = g;

    float nc = 0.f;
    if (do_noise[b] < NOISE_PROB) {
        float S = 0.f, Q = 0.f;
        #pragma unroll 8
        for (int i = 0; i < NB_; i++) { S += g_psum[b * NB_ + i]; Q += g_psq[b * NB_ + i]; }
        const float N = (float)T_;
        float var = (Q - S * S / N) / (N - 1.0f);
        var = fmaxf(var, 0.f);
        float sd = g * sqrtf(var);       // std(x * g) = g * std(x), g > 0
        sd = fmaxf(sd, 1e-4f);           // clip
        nc = sd * noise_scales[b];
    }
    g_ncoef[b] = nc;

    const int h = halves[b];
    g_half[b] = h;
    g_invk[b] = 1.0f / (float)(2 * h + 1);

    int mode = 0;
    if (do_filter[b] < FILTER_PROB) mode = (low_coin[b] < 0.5f) ? 1 : 2;
    g_mode[b] = mode;
}

// ---------------------------------------------------------------------------
// Pass 3: main elementwise + moving-average kernel.
//   mode 0: pure float4 streaming (no SMEM)
//   mode 1/2: SMEM tile of x2 with halo, per-thread sliding window sum,
//             outputs staged in SMEM then stored as coalesced float4.
// ---------------------------------------------------------------------------
__global__ __launch_bounds__(NT3) void k_main(const float* __restrict__ x,
                                              const float* __restrict__ noise,
                                              float* __restrict__ out) {
    const int b  = blockIdx.y;
    const int t0 = blockIdx.x * TILE;
    const int mode = g_mode[b];
    const float gain = g_gain[b];
    const float nc   = g_ncoef[b];
    const size_t base = (size_t)b * T_;
    const int count = min(TILE, T_ - t0);   // always a multiple of 16

    if (mode == 0) {
        // Streaming path. T_ and TILE divisible by 4 -> full float4 coverage.
        const int n4 = count >> 2;
        const float4* xv = (const float4*)(x + base + t0);
        const float4* nv = (const float4*)(noise + base + t0);
        float4* ov = (float4*)(out + base + t0);
        if (nc != 0.f) {
            for (int i = threadIdx.x; i < n4; i += NT3) {
                float4 a = xv[i], n = nv[i], o;
                o.x = fmaf(n.x, nc, a.x * gain);
                o.y = fmaf(n.y, nc, a.y * gain);
                o.z = fmaf(n.z, nc, a.z * gain);
                o.w = fmaf(n.w, nc, a.w * gain);
                ov[i] = o;
            }
        } else {
            for (int i = threadIdx.x; i < n4; i += NT3) {
                float4 a = xv[i], o;
                o.x = a.x * gain; o.y = a.y * gain;
                o.z = a.z * gain; o.w = a.w * gain;
                ov[i] = o;
            }
        }
        return;
    }

    // Filter path: build x2 tile (with halo, zero outside [0,T)) in SMEM.
    __shared__ float s [SMEM_PHYS];
    __shared__ float so[OUT_PHYS];    // output staging (SIDX-mapped)
    if (nc != 0.f) {
        for (int i = threadIdx.x; i < SMEM_LOGICAL; i += NT3) {
            const int t = t0 - HALO + i;
            float v = 0.f;
            if (t >= 0 && t < T_) v = fmaf(noise[base + t], nc, x[base + t] * gain);
            s[SIDX(i)] = v;
        }
    } else {
        for (int i = threadIdx.x; i < SMEM_LOGICAL; i += NT3) {
            const int t = t0 - HALO + i;
            float v = 0.f;
            if (t >= 0 && t < T_) v = x[base + t] * gain;
            s[SIDX(i)] = v;
        }
    }
    __syncthreads();

    const int h = g_half[b];
    const float invk = g_invk[b];
    const int j0 = threadIdx.x * PER_TH;
    if (j0 < count) {
        const int c = HALO + j0;   // smem logical index of first sample
        float sum = 0.f;
        for (int d = -h; d <= h; d++) sum += s[SIDX(c + d)];

        #pragma unroll
        for (int j = 0; j < PER_TH; j++) {
            const float ctr = s[SIDX(c + j)];
            const float low = sum * invk;
            so[SIDX(j0 + j)] = (mode == 1) ? low : (ctr - low);
            sum += s[SIDX(c + j + 1 + h)] - s[SIDX(c + j - h)];
        }
    }
    __syncthreads();

    // Coalesced float4 store of staged outputs (scalar LDS reads are
    // conflict-free: aligned groups of 4 never cross a 32-stride boundary).
    float4* ov = (float4*)(out + base + t0);
    for (int i = threadIdx.x * 4; i < count; i += NT3 * 4) {
        float4 o;
        o.x = so[SIDX(i)];
        o.y = so[SIDX(i + 1)];
        o.z = so[SIDX(i + 2)];
        o.w = so[SIDX(i + 3)];
        ov[i >> 2] = o;
    }
}

// ---------------------------------------------------------------------------
extern "C" void kernel_launch(void* const* d_in, const int* in_sizes, int n_in,
                              void* d_out, int out_size) {
    const float* x            = (const float*)d_in[0];
    const float* gains        = (const float*)d_in[1];
    const float* noise_scales = (const float*)d_in[2];
    const float* noise        = (const float*)d_in[3];
    const float* do_gain      = (const float*)d_in[4];
    const float* do_noise     = (const float*)d_in[5];
    const float* do_filter    = (const float*)d_in[6];
    const float* low_coin     = (const float*)d_in[7];
    const int*   halves       = (const int*)  d_in[8];
    float* out = (float*)d_out;

    dim3 g1(NB_, B_);
    k_reduce<<<g1, 256>>>(x, do_noise);
    k_finalize<<<1, 128>>>(gains, noise_scales, do_gain, do_noise,
                           do_filter, low_coin, halves);
    dim3 g3((T_ + TILE - 1) / TILE, B_);
    k_main<<<g3, NT3>>>(x, noise, out);
}